// round 2
// baseline (speedup 1.0000x reference)
#include <cuda_runtime.h>
#include <math.h>

#define BB   4
#define NPTS 4096
#define GG   4096
#define KNN  8
#define HH   64
#define EPSBN 1e-5f

// ---------------- scratch (static device globals; no allocations) ----------------
__device__ int   g_idx [BB*GG*KNN];
__device__ float g_vol [BB*HH*GG];     // buffer id 0
__device__ float g_tmp [BB*HH*GG];     // buffer id 1
__device__ float g_h1  [BB*HH*GG];     // buffer id 2
__device__ float g_vol8[BB*HH*512];    // buffer id 3
__device__ float g_st1 [6*64];         // per-channel sum   (stat slots)
__device__ float g_st2 [6*64];         // per-channel sumsq
__device__ float g_pooled[BB*64];

__device__ __forceinline__ float* pick(int id) {
    switch (id) {
        case 0: return g_vol;
        case 1: return g_tmp;
        case 2: return g_h1;
        default: return g_vol8;
    }
}

__device__ __forceinline__ float gelu_tanh(float x) {
    float x3 = x * x * x;
    float t  = tanhf(0.7978845608028654f * (x + 0.044715f * x3));
    return 0.5f * x * (1.0f + t);
}

// -------- packed f32x2 helpers (FFMA2: 2 FMA per issue slot) --------
typedef unsigned long long ull;
__device__ __forceinline__ ull pk(float lo, float hi) {
    ull r; asm("mov.b64 %0, {%1,%2};" : "=l"(r) : "f"(lo), "f"(hi)); return r;
}
__device__ __forceinline__ ull pk2(float2 f) { return pk(f.x, f.y); }
__device__ __forceinline__ void upk(ull v, float& lo, float& hi) {
    asm("mov.b64 {%0,%1}, %2;" : "=f"(lo), "=f"(hi) : "l"(v));
}
__device__ __forceinline__ ull fma2(ull a, ull b, ull c) {
    ull d; asm("fma.rn.f32x2 %0, %1, %2, %3;" : "=l"(d) : "l"(a), "l"(b), "l"(c)); return d;
}

// ---------------- KNN: 2 threads per voxel, stable merge ----------------
// 256 blocks x 128 threads. Block covers 64 voxels; thread (half, vl):
// half in {0,1} scans points [half*2048, half*2048+2048).
__global__ void knn_kernel(const float* __restrict__ pos) {
    __shared__ float4 tile[2][64];
    __shared__ float  sbd[128][KNN];
    __shared__ int    sbi[128][KNN];

    // zero BN stat accumulators once per run (block 0 only; stats consumed by later launches)
    if (blockIdx.x == 0) {
        for (int i = threadIdx.x; i < 6 * 64; i += 128) { g_st1[i] = 0.0f; g_st2[i] = 0.0f; }
    }

    int b   = blockIdx.x >> 6;
    int vl  = threadIdx.x & 63;
    int half= threadIdx.x >> 6;
    int g   = ((blockIdx.x & 63) << 6) + vl;

    int gi = g >> 8, gj = (g >> 4) & 15, gk = g & 15;
    const float step = 2.0f / 15.0f;
    float gx = -1.0f + step * gi;
    float gy = -1.0f + step * gj;
    float gz = -1.0f + step * gk;
    float ax = -2.0f * gx, ay = -2.0f * gy, az = -2.0f * gz;

    float bd[KNN]; int bi[KNN];
#pragma unroll
    for (int j = 0; j < KNN; j++) { bd[j] = 3.4e38f; bi[j] = 0; }

    const float* pb = pos + ((size_t)b * NPTS + half * 2048) * 3;

    for (int t0 = 0; t0 < 2048; t0 += 64) {
        __syncthreads();
        {
            int n = t0 + vl;
            float px = pb[n * 3 + 0], py = pb[n * 3 + 1], pz = pb[n * 3 + 2];
            tile[half][vl] = make_float4(px, py, pz, px * px + py * py + pz * pz);
        }
        __syncthreads();
#pragma unroll 2
        for (int t = 0; t < 64; t += 2) {
            float4 p = tile[half][t];
            float4 q = tile[half][t + 1];
            float e0 = fmaf(ax, p.x, fmaf(ay, p.y, fmaf(az, p.z, p.w)));
            float e1 = fmaf(ax, q.x, fmaf(ay, q.y, fmaf(az, q.z, q.w)));
            if (e0 < bd[KNN - 1]) {
                int n = half * 2048 + t0 + t;
#pragma unroll
                for (int j = KNN - 1; j >= 1; --j) {
                    if (e0 < bd[j - 1])  { bd[j] = bd[j - 1]; bi[j] = bi[j - 1]; }
                    else if (e0 < bd[j]) { bd[j] = e0;        bi[j] = n; }
                }
                if (e0 < bd[0]) { bd[0] = e0; bi[0] = n; }
            }
            if (e1 < bd[KNN - 1]) {
                int n = half * 2048 + t0 + t + 1;
#pragma unroll
                for (int j = KNN - 1; j >= 1; --j) {
                    if (e1 < bd[j - 1])  { bd[j] = bd[j - 1]; bi[j] = bi[j - 1]; }
                    else if (e1 < bd[j]) { bd[j] = e1;        bi[j] = n; }
                }
                if (e1 < bd[0]) { bd[0] = e1; bi[0] = n; }
            }
        }
    }

#pragma unroll
    for (int j = 0; j < KNN; j++) { sbd[threadIdx.x][j] = bd[j]; sbi[threadIdx.x][j] = bi[j]; }
    __syncthreads();

    if (threadIdx.x < 64) {
        // merge sorted lists: row tid (points 0..2047, lower idx) and row tid+64.
        // tie (equal e) -> lower index first == take A. Matches jax.lax.top_k order.
        int ia = 0, ibp = 0;
        int base = (b * GG + g) * KNN;
#pragma unroll
        for (int j = 0; j < KNN; j++) {
            float eA = sbd[threadIdx.x][ia], eB = sbd[threadIdx.x + 64][ibp];
            if (eA <= eB) { g_idx[base + j] = sbi[threadIdx.x][ia]; ia++; }
            else          { g_idx[base + j] = sbi[threadIdx.x + 64][ibp]; ibp++; }
        }
    }
}

// ---------------- Bipartite conv MLP ----------------
// 16384 blocks x 64 threads; 1 voxel per block, thread = channel h.
// pe_w2/up_w columns held in packed f32x2 registers.
__global__ void mlp_kernel(const float* __restrict__ pos, const float* __restrict__ xf,
                           const float* __restrict__ pe_w1, const float* __restrict__ pe_b1,
                           const float* __restrict__ pe_w2, const float* __restrict__ pe_b2,
                           const float* __restrict__ f_w,   const float* __restrict__ f_b,
                           const float* __restrict__ up_w,  const float* __restrict__ up_b) {
    __shared__ float s_w1[192], s_fw[192];
    __shared__ float s_b1[64], s_b2[64], s_fb[64], s_ub[64];
    __shared__ __align__(8) float s_t[64];

    int h = threadIdx.x;
    s_w1[h] = pe_w1[h];       s_w1[h + 64] = pe_w1[h + 64];   s_w1[h + 128] = pe_w1[h + 128];
    s_fw[h] = f_w[h];         s_fw[h + 64] = f_w[h + 64];     s_fw[h + 128] = f_w[h + 128];
    s_b1[h] = pe_b1[h]; s_b2[h] = pe_b2[h]; s_fb[h] = f_b[h]; s_ub[h] = up_b[h];

    ull wcol2[32];
#pragma unroll
    for (int j = 0; j < 32; j++)
        wcol2[j] = pk(pe_w2[(2 * j) * 64 + h], pe_w2[(2 * j + 1) * 64 + h]);
    __syncthreads();

    int b = blockIdx.x >> 12;
    int g = blockIdx.x & 4095;
    int gi = g >> 8, gj = (g >> 4) & 15, gk = g & 15;
    const float step = 2.0f / 15.0f;
    float gx = -1.0f + step * gi;
    float gy = -1.0f + step * gj;
    float gz = -1.0f + step * gk;

    const int* ib = g_idx + (b * GG + g) * KNN;
    float acc = 0.0f;

    for (int k = 0; k < KNN; k++) {
        int n = ib[k];
        const float* pp = pos + ((size_t)b * NPTS + n) * 3;
        float rx = pp[0] - gx, ry = pp[1] - gy, rz = pp[2] - gz;
        float t1 = rx * s_w1[h] + ry * s_w1[64 + h] + rz * s_w1[128 + h] + s_b1[h];
        s_t[h] = gelu_tanh(t1);
        __syncthreads();
        ull a2 = 0;  // (+0,+0)
#pragma unroll
        for (int j = 0; j < 32; j++) a2 = fma2(pk2(((const float2*)s_t)[j]), wcol2[j], a2);
        float plo, phi; upk(a2, plo, phi);
        float pe = plo + phi + s_b2[h];
        const float* xp = xf + ((size_t)b * NPTS + n) * 3;
        float fm = xp[0] * s_fw[h] + xp[1] * s_fw[64 + h] + xp[2] * s_fw[128 + h] + s_fb[h];
        acc = fmaf(pe, fm, acc);
        __syncthreads();
    }
    acc *= 0.125f;

#pragma unroll
    for (int j = 0; j < 32; j++)
        wcol2[j] = pk(up_w[(2 * j) * 64 + h], up_w[(2 * j + 1) * 64 + h]);
    s_t[h] = acc;
    __syncthreads();
    ull a2 = 0;
#pragma unroll
    for (int j = 0; j < 32; j++) a2 = fma2(pk2(((const float2*)s_t)[j]), wcol2[j], a2);
    float olo, ohi; upk(a2, olo, ohi);
    float o = gelu_tanh(olo + ohi + s_ub[h]);

    int s = (g & 15) * 256 + ((g >> 4) & 15) * 16 + (g >> 8);
    g_vol[(b * 64 + h) * GG + s] = o;
}

// ---------------- Conv3D 3x3x3 SAME, 64->64 channels, f32x2 packed ----------------
// Optional BN(normalize)+ReLU applied on input staging (in_stat>=0).
// Always accumulates output per-channel sum/sumsq into stat slot out_stat.
template <int R, int COP>
__global__ void conv3d_kernel(int in_id, const float* __restrict__ w,
                              const float* __restrict__ bias, int out_id,
                              int in_stat, int out_stat) {
    constexpr int P = R + 2, S = R * R * R, NT = R * R;
    __shared__ __align__(16) float sl[P * P * P];
    __shared__ float wsh[COP * 64 * 27];

    const float* in = pick(in_id);
    float* out = pick(out_id);

    int tid = threadIdx.x;
    int co0 = blockIdx.x * COP;
    int b = blockIdx.y;

    for (int i = tid; i < COP * 64 * 27; i += NT) {
        int col = i / 1728, r = i - col * 1728;
        wsh[i] = w[(co0 + col) * 1728 + r];
    }
    for (int i = tid; i < P * P * P; i += NT) sl[i] = 0.0f;

    int z = tid / R, y = tid - z * R;
    ull acc2[COP][R / 2];
#pragma unroll
    for (int c = 0; c < COP; c++)
#pragma unroll
        for (int j = 0; j < R / 2; j++) acc2[c][j] = 0;

    const float invc = 1.0f / (float)(BB * S);

    for (int ci = 0; ci < 64; ci++) {
        float mean = 0.0f, rstd = 0.0f;
        if (in_stat >= 0) {
            float m = g_st1[in_stat * 64 + ci] * invc;
            float v = g_st2[in_stat * 64 + ci] * invc - m * m;
            mean = m; rstd = rsqrtf(v + EPSBN);
        }
        __syncthreads();
        const float* ip = in + (size_t)(b * 64 + ci) * S;
        for (int i = tid; i < S; i += NT) {
            float v = ip[i];
            if (in_stat >= 0) v = fmaxf((v - mean) * rstd, 0.0f);
            int zz = i / (R * R), rem = i - zz * (R * R);
            int yy = rem / R, xx = rem - yy * R;
            sl[(zz + 1) * P * P + (yy + 1) * P + (xx + 1)] = v;
        }
        __syncthreads();
#pragma unroll
        for (int dz = 0; dz < 3; dz++) {
#pragma unroll
            for (int dy = 0; dy < 3; dy++) {
                const float2* rp = (const float2*)&sl[(z + dz) * P * P + (y + dy) * P];
                float2 a[R / 2 + 1];
#pragma unroll
                for (int j = 0; j <= R / 2; j++) a[j] = rp[j];
                ull mid[R / 2];
#pragma unroll
                for (int j = 0; j < R / 2; j++) mid[j] = pk(a[j].y, a[j + 1].x);
#pragma unroll
                for (int c = 0; c < COP; c++) {
                    const float* wp = &wsh[c * 1728 + ci * 27 + (dz * 3 + dy) * 3];
                    ull W0 = pk(wp[0], wp[0]);
                    ull W1 = pk(wp[1], wp[1]);
                    ull W2 = pk(wp[2], wp[2]);
#pragma unroll
                    for (int j = 0; j < R / 2; j++)
                        acc2[c][j] = fma2(W0, pk2(a[j]),
                                     fma2(W1, mid[j],
                                     fma2(W2, pk2(a[j + 1]), acc2[c][j])));
                }
            }
        }
    }

    int lane = tid & 31;
#pragma unroll
    for (int c = 0; c < COP; c++) {
        float bv = bias[co0 + c];
        float2* op = (float2*)(out + (size_t)(b * 64 + co0 + c) * S + z * R * R + y * R);
        float s1 = 0.0f, s2 = 0.0f;
#pragma unroll
        for (int j = 0; j < R / 2; j++) {
            float lo, hi; upk(acc2[c][j], lo, hi);
            lo += bv; hi += bv;
            op[j] = make_float2(lo, hi);
            s1 += lo + hi;
            s2 += lo * lo + hi * hi;
        }
#pragma unroll
        for (int off = 16; off; off >>= 1) {
            s1 += __shfl_xor_sync(0xffffffffu, s1, off);
            s2 += __shfl_xor_sync(0xffffffffu, s2, off);
        }
        if (lane == 0) {
            atomicAdd(&g_st1[out_stat * 64 + co0 + c], s1);
            atomicAdd(&g_st2[out_stat * 64 + co0 + c], s2);
        }
    }
}

// ---------------- residual add (BN of h1 via stat slot 1) + ReLU + 2x2x2 maxpool -----
__global__ void respool_kernel() {
    int i = blockIdx.x * blockDim.x + threadIdx.x;
    if (i >= BB * 64 * 512) return;
    int x = i & 7, y = (i >> 3) & 7, z = (i >> 6) & 7, bc = i >> 9;
    int c = bc & 63;
    const float invc = 1.0f / (float)(BB * 4096);
    float m = g_st1[64 + c] * invc;
    float v = g_st2[64 + c] * invc - m * m;
    float r = rsqrtf(v + EPSBN);
    const float* vp = g_vol + (size_t)bc * 4096;
    const float* hp = g_h1 + (size_t)bc * 4096;
    float mx = -3.4e38f;
#pragma unroll
    for (int dz = 0; dz < 2; dz++)
#pragma unroll
        for (int dy = 0; dy < 2; dy++)
#pragma unroll
            for (int dx = 0; dx < 2; dx++) {
                int idx = (2 * z + dz) * 256 + (2 * y + dy) * 16 + (2 * x + dx);
                float t = fmaxf(vp[idx] + (hp[idx] - m) * r, 0.0f);
                mx = fmaxf(mx, t);
            }
    g_vol8[i] = mx;
}

// ---------------- final: residual(BN stat3)+ReLU, BN over result, affine, pool ------
__global__ void final_kernel(const float* __restrict__ on_g, const float* __restrict__ on_b) {
    __shared__ float sres[2048];
    __shared__ float rb1[8], rb2[8];
    __shared__ float smr[2];

    int c = blockIdx.x;
    int t = threadIdx.x;
    const float invc = 1.0f / (float)(BB * 512);
    float m3 = g_st1[3 * 64 + c] * invc;
    float v3 = g_st2[3 * 64 + c] * invc - m3 * m3;
    float r3 = rsqrtf(v3 + EPSBN);

    float s1 = 0.0f, s2 = 0.0f;
    for (int i = t; i < 2048; i += 256) {
        int b = i >> 9, s = i & 511;
        size_t off = (size_t)(b * 64 + c) * 512 + s;
        float val = fmaxf(g_vol8[off] + (g_h1[off] - m3) * r3, 0.0f);
        sres[i] = val;
        s1 += val; s2 += val * val;
    }
    int w = t >> 5, l = t & 31;
#pragma unroll
    for (int off = 16; off; off >>= 1) {
        s1 += __shfl_xor_sync(0xffffffffu, s1, off);
        s2 += __shfl_xor_sync(0xffffffffu, s2, off);
    }
    if (l == 0) { rb1[w] = s1; rb2[w] = s2; }
    __syncthreads();
    if (t == 0) {
        float a = 0.0f, q = 0.0f;
#pragma unroll
        for (int j = 0; j < 8; j++) { a += rb1[j]; q += rb2[j]; }
        float m4 = a * invc;
        float v4 = q * invc - m4 * m4;
        smr[0] = m4; smr[1] = rsqrtf(v4 + EPSBN);
    }
    __syncthreads();
    float m4 = smr[0], r4 = smr[1];

    if (w < 4) {  // warp w handles batch b=w
        float s = 0.0f;
#pragma unroll
        for (int k = 0; k < 16; k++) s += sres[w * 512 + l + k * 32];
#pragma unroll
        for (int off = 16; off; off >>= 1) s += __shfl_xor_sync(0xffffffffu, s, off);
        if (l == 0)
            g_pooled[w * 64 + c] = (s * (1.0f / 512.0f) - m4) * r4 * on_g[c] + on_b[c];
    }
}

// ---------------- head: pooled @ ro_w + ro_b ----------------
__global__ void head_kernel(const float* __restrict__ ro_w, const float* __restrict__ ro_b,
                            float* __restrict__ out) {
    int t = threadIdx.x;           // 64 threads: (b,o)
    int b = t >> 4, o = t & 15;
    float a = ro_b[o];
#pragma unroll
    for (int j = 0; j < 64; j++) a = fmaf(g_pooled[b * 64 + j], ro_w[j * 16 + o], a);
    out[b * 16 + o] = a;
}

// ---------------- launch ----------------
extern "C" void kernel_launch(void* const* d_in, const int* in_sizes, int n_in,
                              void* d_out, int out_size) {
    const float* pos   = (const float*)d_in[0];
    const float* xf    = (const float*)d_in[1];
    const float* pe_w1 = (const float*)d_in[2];
    const float* pe_b1 = (const float*)d_in[3];
    const float* pe_w2 = (const float*)d_in[4];
    const float* pe_b2 = (const float*)d_in[5];
    const float* f_w   = (const float*)d_in[6];
    const float* f_b   = (const float*)d_in[7];
    const float* up_w  = (const float*)d_in[8];
    const float* up_b  = (const float*)d_in[9];
    const float* conv_w= (const float*)d_in[10];
    const float* conv_b= (const float*)d_in[11];
    const float* on_g  = (const float*)d_in[12];
    const float* on_b  = (const float*)d_in[13];
    const float* ro_w  = (const float*)d_in[14];
    const float* ro_b  = (const float*)d_in[15];
    float* out = (float*)d_out;

    const int W1 = 64 * 64 * 27;

    knn_kernel<<<256, 128>>>(pos);
    mlp_kernel<<<16384, 64>>>(pos, xf, pe_w1, pe_b1, pe_w2, pe_b2, f_w, f_b, up_w, up_b);

    // block 0 (16^3): convA -> stats0 ; convB (norm stats0 on load) -> stats1
    conv3d_kernel<16, 2><<<dim3(32, 4), 256>>>(0, conv_w + 0 * W1, conv_b + 0,  1, -1, 0);
    conv3d_kernel<16, 2><<<dim3(32, 4), 256>>>(1, conv_w + 1 * W1, conv_b + 64, 2,  0, 1);
    respool_kernel<<<512, 256>>>();

    // block 1 (8^3): convC -> stats2 ; convD (norm stats2) -> stats3
    conv3d_kernel<8, 1><<<dim3(64, 4), 64>>>(3, conv_w + 2 * W1, conv_b + 128, 1, -1, 2);
    conv3d_kernel<8, 1><<<dim3(64, 4), 64>>>(1, conv_w + 3 * W1, conv_b + 192, 2,  2, 3);

    final_kernel<<<64, 256>>>(on_g, on_b);
    head_kernel<<<1, 64>>>(ro_w, ro_b, out);
}

// round 4
// speedup vs baseline: 1.8395x; 1.8395x over previous
#include <cuda_runtime.h>
#include <math.h>

#define BB   4
#define NPTS 4096
#define GG   4096
#define KNN  8
#define HH   64
#define EPSBN 1e-5f

// ---------------- scratch (static device globals; no allocations) ----------------
__device__ int   g_idx [BB*GG*KNN];
__device__ float g_vol [BB*HH*GG];     // buffer id 0
__device__ float g_tmp [BB*HH*GG];     // buffer id 1
__device__ float g_h1  [BB*HH*GG];     // buffer id 2
__device__ float g_vol8[BB*HH*512];    // buffer id 3
__device__ float g_st1 [6*64];         // per-channel sum   (stat slots)
__device__ float g_st2 [6*64];         // per-channel sumsq
__device__ float g_pooled[BB*64];

__device__ __forceinline__ float* pick(int id) {
    switch (id) {
        case 0: return g_vol;
        case 1: return g_tmp;
        case 2: return g_h1;
        default: return g_vol8;
    }
}

__device__ __forceinline__ float gelu_tanh(float x) {
    float x3 = x * x * x;
    float t  = tanhf(0.7978845608028654f * (x + 0.044715f * x3));
    return 0.5f * x * (1.0f + t);
}

// -------- packed f32x2 helpers (used in MLP only, where operands are pair-resident) ----
typedef unsigned long long ull;
__device__ __forceinline__ ull pk(float lo, float hi) {
    ull r; asm("mov.b64 %0, {%1,%2};" : "=l"(r) : "f"(lo), "f"(hi)); return r;
}
__device__ __forceinline__ ull pk2(float2 f) { return pk(f.x, f.y); }
__device__ __forceinline__ void upk(ull v, float& lo, float& hi) {
    asm("mov.b64 {%0,%1}, %2;" : "=f"(lo), "=f"(hi) : "l"(v));
}
__device__ __forceinline__ ull fma2(ull a, ull b, ull c) {
    ull d; asm("fma.rn.f32x2 %0, %1, %2, %3;" : "=l"(d) : "l"(a), "l"(b), "l"(c)); return d;
}

// ---------------- KNN: 2 threads per voxel, stable merge ----------------
__global__ void knn_kernel(const float* __restrict__ pos) {
    __shared__ float4 tile[2][64];
    __shared__ float  sbd[128][KNN];
    __shared__ int    sbi[128][KNN];

    if (blockIdx.x == 0) {
        for (int i = threadIdx.x; i < 6 * 64; i += 128) { g_st1[i] = 0.0f; g_st2[i] = 0.0f; }
    }

    int b   = blockIdx.x >> 6;
    int vl  = threadIdx.x & 63;
    int half= threadIdx.x >> 6;
    int g   = ((blockIdx.x & 63) << 6) + vl;

    int gi = g >> 8, gj = (g >> 4) & 15, gk = g & 15;
    const float step = 2.0f / 15.0f;
    float gx = -1.0f + step * gi;
    float gy = -1.0f + step * gj;
    float gz = -1.0f + step * gk;
    float ax = -2.0f * gx, ay = -2.0f * gy, az = -2.0f * gz;

    float bd[KNN]; int bi[KNN];
#pragma unroll
    for (int j = 0; j < KNN; j++) { bd[j] = 3.4e38f; bi[j] = 0; }

    const float* pb = pos + ((size_t)b * NPTS + half * 2048) * 3;

    for (int t0 = 0; t0 < 2048; t0 += 64) {
        __syncthreads();
        {
            int n = t0 + vl;
            float px = pb[n * 3 + 0], py = pb[n * 3 + 1], pz = pb[n * 3 + 2];
            tile[half][vl] = make_float4(px, py, pz, px * px + py * py + pz * pz);
        }
        __syncthreads();
#pragma unroll 2
        for (int t = 0; t < 64; t += 2) {
            float4 p = tile[half][t];
            float4 q = tile[half][t + 1];
            float e0 = fmaf(ax, p.x, fmaf(ay, p.y, fmaf(az, p.z, p.w)));
            float e1 = fmaf(ax, q.x, fmaf(ay, q.y, fmaf(az, q.z, q.w)));
            if (e0 < bd[KNN - 1]) {
                int n = half * 2048 + t0 + t;
#pragma unroll
                for (int j = KNN - 1; j >= 1; --j) {
                    if (e0 < bd[j - 1])  { bd[j] = bd[j - 1]; bi[j] = bi[j - 1]; }
                    else if (e0 < bd[j]) { bd[j] = e0;        bi[j] = n; }
                }
                if (e0 < bd[0]) { bd[0] = e0; bi[0] = n; }
            }
            if (e1 < bd[KNN - 1]) {
                int n = half * 2048 + t0 + t + 1;
#pragma unroll
                for (int j = KNN - 1; j >= 1; --j) {
                    if (e1 < bd[j - 1])  { bd[j] = bd[j - 1]; bi[j] = bi[j - 1]; }
                    else if (e1 < bd[j]) { bd[j] = e1;        bi[j] = n; }
                }
                if (e1 < bd[0]) { bd[0] = e1; bi[0] = n; }
            }
        }
    }

#pragma unroll
    for (int j = 0; j < KNN; j++) { sbd[threadIdx.x][j] = bd[j]; sbi[threadIdx.x][j] = bi[j]; }
    __syncthreads();

    if (threadIdx.x < 64) {
        int ia = 0, ibp = 0;
        int base = (b * GG + g) * KNN;
#pragma unroll
        for (int j = 0; j < KNN; j++) {
            float eA = sbd[threadIdx.x][ia], eB = sbd[threadIdx.x + 64][ibp];
            if (eA <= eB) { g_idx[base + j] = sbi[threadIdx.x][ia]; ia++; }
            else          { g_idx[base + j] = sbi[threadIdx.x + 64][ibp]; ibp++; }
        }
    }
}

// ---------------- Bipartite conv MLP ----------------
__global__ void mlp_kernel(const float* __restrict__ pos, const float* __restrict__ xf,
                           const float* __restrict__ pe_w1, const float* __restrict__ pe_b1,
                           const float* __restrict__ pe_w2, const float* __restrict__ pe_b2,
                           const float* __restrict__ f_w,   const float* __restrict__ f_b,
                           const float* __restrict__ up_w,  const float* __restrict__ up_b) {
    __shared__ float s_w1[192], s_fw[192];
    __shared__ float s_b1[64], s_b2[64], s_fb[64], s_ub[64];
    __shared__ __align__(8) float s_t[64];

    int h = threadIdx.x;
    s_w1[h] = pe_w1[h];       s_w1[h + 64] = pe_w1[h + 64];   s_w1[h + 128] = pe_w1[h + 128];
    s_fw[h] = f_w[h];         s_fw[h + 64] = f_w[h + 64];     s_fw[h + 128] = f_w[h + 128];
    s_b1[h] = pe_b1[h]; s_b2[h] = pe_b2[h]; s_fb[h] = f_b[h]; s_ub[h] = up_b[h];

    ull wcol2[32];
#pragma unroll
    for (int j = 0; j < 32; j++)
        wcol2[j] = pk(pe_w2[(2 * j) * 64 + h], pe_w2[(2 * j + 1) * 64 + h]);
    __syncthreads();

    int b = blockIdx.x >> 12;
    int g = blockIdx.x & 4095;
    int gi = g >> 8, gj = (g >> 4) & 15, gk = g & 15;
    const float step = 2.0f / 15.0f;
    float gx = -1.0f + step * gi;
    float gy = -1.0f + step * gj;
    float gz = -1.0f + step * gk;

    const int* ib = g_idx + (b * GG + g) * KNN;
    float acc = 0.0f;

    for (int k = 0; k < KNN; k++) {
        int n = ib[k];
        const float* pp = pos + ((size_t)b * NPTS + n) * 3;
        float rx = pp[0] - gx, ry = pp[1] - gy, rz = pp[2] - gz;
        float t1 = rx * s_w1[h] + ry * s_w1[64 + h] + rz * s_w1[128 + h] + s_b1[h];
        s_t[h] = gelu_tanh(t1);
        __syncthreads();
        ull a2 = 0;
#pragma unroll
        for (int j = 0; j < 32; j++) a2 = fma2(pk2(((const float2*)s_t)[j]), wcol2[j], a2);
        float plo, phi; upk(a2, plo, phi);
        float pe = plo + phi + s_b2[h];
        const float* xp = xf + ((size_t)b * NPTS + n) * 3;
        float fm = xp[0] * s_fw[h] + xp[1] * s_fw[64 + h] + xp[2] * s_fw[128 + h] + s_fb[h];
        acc = fmaf(pe, fm, acc);
        __syncthreads();
    }
    acc *= 0.125f;

#pragma unroll
    for (int j = 0; j < 32; j++)
        wcol2[j] = pk(up_w[(2 * j) * 64 + h], up_w[(2 * j + 1) * 64 + h]);
    s_t[h] = acc;
    __syncthreads();
    ull a2 = 0;
#pragma unroll
    for (int j = 0; j < 32; j++) a2 = fma2(pk2(((const float2*)s_t)[j]), wcol2[j], a2);
    float olo, ohi; upk(a2, olo, ohi);
    float o = gelu_tanh(olo + ohi + s_ub[h]);

    int s = (g & 15) * 256 + ((g >> 4) & 15) * 16 + (g >> 8);
    g_vol[(b * 64 + h) * GG + s] = o;
}

// ---------------- Conv3D 3x3x3 SAME, 64->64 ch, scalar FFMA, z-slab split ----------------
// Block: 2*R*ZB threads; thread = (xh, y, zl) computes XS=R/2 outputs along x for COP
// channels on z-slab [z0, z0+ZB). Grid: (64/COP co-groups, R/ZB slabs, B).
// Optional BN(in_stat)+ReLU fused on input staging; output sum/sumsq atomically
// accumulated into stat slot out_stat.
template <int R, int ZB, int COP>
__global__ void conv3d_kernel(int in_id, const float* __restrict__ w,
                              const float* __restrict__ bias, int out_id,
                              int in_stat, int out_stat) {
    constexpr int XS = R / 2;
    constexpr int PX = R + 4;          // padded row (16B-aligned rows)
    constexpr int PY = R + 2;
    constexpr int PZ = ZB + 2;
    constexpr int NT = 2 * R * ZB;
    constexpr int S  = R * R * R;
    constexpr int CELLS = PZ * R * R;  // staged (in-range candidate) cells per ci

    __shared__ __align__(16) float sl[PZ * PY * PX];
    __shared__ __align__(16) float4 wsh4[COP * 64 * 9];

    const float* in = pick(in_id);
    float* out = pick(out_id);

    int tid = threadIdx.x;
    int co0 = blockIdx.x * COP;
    int z0  = blockIdx.y * ZB;
    int b   = blockIdx.z;

    // pack weights: wsh4[(c*64+ci)*9 + t] = (w0,w1,w2,-) of tap-row t
#pragma unroll
    for (int it = 0; it < (COP * 64 * 9) / NT; it++) {
        int i = tid + it * NT;
        int c = i / 576, rem = i - c * 576;
        const float* wp = w + (co0 + c) * 1728 + rem * 3;
        wsh4[i] = make_float4(wp[0], wp[1], wp[2], 0.0f);
    }
    for (int i = tid; i < PZ * PY * PX; i += NT) sl[i] = 0.0f;

    int xh = tid & 1;
    int y  = (tid >> 1) & (R - 1);
    int zl = tid / (2 * R);

    float acc[COP][XS];
#pragma unroll
    for (int c = 0; c < COP; c++)
#pragma unroll
        for (int x = 0; x < XS; x++) acc[c][x] = 0.0f;

    const float invc = 1.0f / (float)(BB * S);

    for (int ci = 0; ci < 64; ci++) {
        float mean = 0.0f, rstd = 0.0f;
        if (in_stat >= 0) {
            float m = g_st1[in_stat * 64 + ci] * invc;
            float v = g_st2[in_stat * 64 + ci] * invc - m * m;
            mean = m; rstd = rsqrtf(v + EPSBN);
        }
        __syncthreads();
        const float* ip = in + (size_t)(b * 64 + ci) * S;
#pragma unroll
        for (int it = 0; it < CELLS / NT; it++) {
            int i = tid + it * NT;
            int zz = i / (R * R), rem = i - zz * (R * R);
            int yy = rem / R, xx = rem - yy * R;
            int gz = z0 - 1 + zz;
            if (gz >= 0 && gz < R) {
                float v = ip[gz * R * R + yy * R + xx];
                if (in_stat >= 0) v = fmaxf((v - mean) * rstd, 0.0f);
                sl[(zz * PY + (yy + 1)) * PX + (xx + 1)] = v;
            }
        }
        __syncthreads();

#pragma unroll
        for (int dz = 0; dz < 3; dz++) {
#pragma unroll
            for (int dy = 0; dy < 3; dy++) {
                const float* base = &sl[((zl + dz) * PY + (y + dy)) * PX + xh * XS];
                float r[XS + 4];
#pragma unroll
                for (int q = 0; q < (XS + 4) / 4; q++)
                    *(float4*)&r[4 * q] = *(const float4*)&base[4 * q];
#pragma unroll
                for (int c = 0; c < COP; c++) {
                    float4 wv = wsh4[(c * 64 + ci) * 9 + dz * 3 + dy];
#pragma unroll
                    for (int x = 0; x < XS; x++)
                        acc[c][x] = fmaf(wv.x, r[x],
                                    fmaf(wv.y, r[x + 1],
                                    fmaf(wv.z, r[x + 2], acc[c][x])));
                }
            }
        }
    }

    int lane = tid & 31;
#pragma unroll
    for (int c = 0; c < COP; c++) {
        float bv = bias[co0 + c];
        float* op = out + (size_t)(b * 64 + co0 + c) * S + (z0 + zl) * R * R + y * R + xh * XS;
        float s1 = 0.0f, s2 = 0.0f;
#pragma unroll
        for (int x = 0; x < XS; x++) {
            float v = acc[c][x] + bv;
            acc[c][x] = v;
            s1 += v; s2 += v * v;
        }
#pragma unroll
        for (int q = 0; q < XS / 4; q++)
            *(float4*)&op[4 * q] = *(float4*)&acc[c][4 * q];
#pragma unroll
        for (int off = 16; off; off >>= 1) {
            s1 += __shfl_xor_sync(0xffffffffu, s1, off);
            s2 += __shfl_xor_sync(0xffffffffu, s2, off);
        }
        if (lane == 0) {
            atomicAdd(&g_st1[out_stat * 64 + co0 + c], s1);
            atomicAdd(&g_st2[out_stat * 64 + co0 + c], s2);
        }
    }
}

// ---------------- residual add (BN of conv-out via stat slot 1) + ReLU + maxpool -----
__global__ void respool_kernel() {
    int i = blockIdx.x * blockDim.x + threadIdx.x;
    if (i >= BB * 64 * 512) return;
    int x = i & 7, y = (i >> 3) & 7, z = (i >> 6) & 7, bc = i >> 9;
    int c = bc & 63;
    const float invc = 1.0f / (float)(BB * 4096);
    float m = g_st1[64 + c] * invc;
    float v = g_st2[64 + c] * invc - m * m;
    float r = rsqrtf(v + EPSBN);
    const float* vp = g_vol + (size_t)bc * 4096;
    const float* hp = g_h1 + (size_t)bc * 4096;
    float mx = -3.4e38f;
#pragma unroll
    for (int dz = 0; dz < 2; dz++)
#pragma unroll
        for (int dy = 0; dy < 2; dy++)
#pragma unroll
            for (int dx = 0; dx < 2; dx++) {
                int idx = (2 * z + dz) * 256 + (2 * y + dy) * 16 + (2 * x + dx);
                float t = fmaxf(vp[idx] + (hp[idx] - m) * r, 0.0f);
                mx = fmaxf(mx, t);
            }
    g_vol8[i] = mx;
}

// ---------------- final: residual(BN stat3)+ReLU, BN over result, affine, pool ------
__global__ void final_kernel(const float* __restrict__ on_g, const float* __restrict__ on_b) {
    __shared__ float sres[2048];
    __shared__ float rb1[8], rb2[8];
    __shared__ float smr[2];

    int c = blockIdx.x;
    int t = threadIdx.x;
    const float invc = 1.0f / (float)(BB * 512);
    float m3 = g_st1[3 * 64 + c] * invc;
    float v3 = g_st2[3 * 64 + c] * invc - m3 * m3;
    float r3 = rsqrtf(v3 + EPSBN);

    float s1 = 0.0f, s2 = 0.0f;
    for (int i = t; i < 2048; i += 256) {
        int b = i >> 9, s = i & 511;
        size_t off = (size_t)(b * 64 + c) * 512 + s;
        float val = fmaxf(g_vol8[off] + (g_h1[off] - m3) * r3, 0.0f);
        sres[i] = val;
        s1 += val; s2 += val * val;
    }
    int w = t >> 5, l = t & 31;
#pragma unroll
    for (int off = 16; off; off >>= 1) {
        s1 += __shfl_xor_sync(0xffffffffu, s1, off);
        s2 += __shfl_xor_sync(0xffffffffu, s2, off);
    }
    if (l == 0) { rb1[w] = s1; rb2[w] = s2; }
    __syncthreads();
    if (t == 0) {
        float a = 0.0f, q = 0.0f;
#pragma unroll
        for (int j = 0; j < 8; j++) { a += rb1[j]; q += rb2[j]; }
        float m4 = a * invc;
        float v4 = q * invc - m4 * m4;
        smr[0] = m4; smr[1] = rsqrtf(v4 + EPSBN);
    }
    __syncthreads();
    float m4 = smr[0], r4 = smr[1];

    if (w < 4) {
        float s = 0.0f;
#pragma unroll
        for (int k = 0; k < 16; k++) s += sres[w * 512 + l + k * 32];
#pragma unroll
        for (int off = 16; off; off >>= 1) s += __shfl_xor_sync(0xffffffffu, s, off);
        if (l == 0)
            g_pooled[w * 64 + c] = (s * (1.0f / 512.0f) - m4) * r4 * on_g[c] + on_b[c];
    }
}

// ---------------- head ----------------
__global__ void head_kernel(const float* __restrict__ ro_w, const float* __restrict__ ro_b,
                            float* __restrict__ out) {
    int t = threadIdx.x;
    int b = t >> 4, o = t & 15;
    float a = ro_b[o];
#pragma unroll
    for (int j = 0; j < 64; j++) a = fmaf(g_pooled[b * 64 + j], ro_w[j * 16 + o], a);
    out[b * 16 + o] = a;
}

// ---------------- launch ----------------
extern "C" void kernel_launch(void* const* d_in, const int* in_sizes, int n_in,
                              void* d_out, int out_size) {
    const float* pos   = (const float*)d_in[0];
    const float* xf    = (const float*)d_in[1];
    const float* pe_w1 = (const float*)d_in[2];
    const float* pe_b1 = (const float*)d_in[3];
    const float* pe_w2 = (const float*)d_in[4];
    const float* pe_b2 = (const float*)d_in[5];
    const float* f_w   = (const float*)d_in[6];
    const float* f_b   = (const float*)d_in[7];
    const float* up_w  = (const float*)d_in[8];
    const float* up_b  = (const float*)d_in[9];
    const float* conv_w= (const float*)d_in[10];
    const float* conv_b= (const float*)d_in[11];
    const float* on_g  = (const float*)d_in[12];
    const float* on_b  = (const float*)d_in[13];
    const float* ro_w  = (const float*)d_in[14];
    const float* ro_b  = (const float*)d_in[15];
    float* out = (float*)d_out;

    const int W1 = 64 * 64 * 27;

    knn_kernel<<<256, 128>>>(pos);
    mlp_kernel<<<16384, 64>>>(pos, xf, pe_w1, pe_b1, pe_w2, pe_b2, f_w, f_b, up_w, up_b);

    // block 0 (16^3): convA -> stats0 ; convB (norm stats0 on load) -> stats1
    conv3d_kernel<16, 4, 2><<<dim3(32, 4, 4), 128>>>(0, conv_w + 0 * W1, conv_b + 0,  1, -1, 0);
    conv3d_kernel<16, 4, 2><<<dim3(32, 4, 4), 128>>>(1, conv_w + 1 * W1, conv_b + 64, 2,  0, 1);
    respool_kernel<<<512, 256>>>();

    // block 1 (8^3): convC -> stats2 ; convD (norm stats2) -> stats3
    conv3d_kernel<8, 4, 2><<<dim3(32, 2, 4), 64>>>(3, conv_w + 2 * W1, conv_b + 128, 1, -1, 2);
    conv3d_kernel<8, 4, 2><<<dim3(32, 2, 4), 64>>>(1, conv_w + 3 * W1, conv_b + 192, 2,  2, 3);

    final_kernel<<<64, 256>>>(on_g, on_b);
    head_kernel<<<1, 64>>>(ro_w, ro_b, out);
}